// round 2
// baseline (speedup 1.0000x reference)
#include <cuda_runtime.h>
#include <math.h>

// Problem dims (fixed by the reference)
#define M_ROWS 16384
#define K_DIM  4096
#define N_DIM  4096

// GEMM tiling
#define BM 128
#define BN 128
#define BK 32
#define PAD 4   // smem row padding (floats) -> 16B-aligned rows, reduced conflicts

// Scratch: per-row signed popcount accumulator s[b] = sum_j sign(h[b,j])*sign(W2[j]).
// Values are exact small integers in fp32, so float atomicAdd is order-independent
// and the result is deterministic.
__device__ float g_s[M_ROWS];

__global__ void zero_s_kernel() {
    int i = blockIdx.x * blockDim.x + threadIdx.x;
    if (i < M_ROWS) g_s[i] = 0.0f;
}

// Fused kernel: C_tile = X_tile @ sign(W1_tile)^T  (fp32 FFMA, exact +/-x products),
// then epilogue reduces sign(C) * sign(W2) over the N-tile into g_s via atomicAdd.
// h is never materialized in global memory.
__global__ __launch_bounds__(256, 2)
void gemm_sign_kernel(const float* __restrict__ X,
                      const float* __restrict__ W1,
                      const float* __restrict__ W2) {
    __shared__ float As[BK][BM + PAD];  // As[k][m], X tile transposed into smem
    __shared__ float Bs[BK][BN + PAD];  // Bs[k][n], sign(W1) tile transposed

    const int bm  = blockIdx.y * BM;
    const int bn  = blockIdx.x * BN;
    const int tid = threadIdx.x;       // 0..255
    const int tx  = tid & 15;          // 16 thread columns
    const int ty  = tid >> 4;          // 16 thread rows

    // Each thread owns an 8x8 micro-tile:
    //   rows: bm + ty*4 + r      (r=0..3)   and bm + 64 + ty*4 + (r-4)  (r=4..7)
    //   cols: bn + tx*4 + c      (c=0..3)   and bn + 64 + tx*4 + (c-4)  (c=4..7)
    float acc[8][8];
#pragma unroll
    for (int r = 0; r < 8; r++)
#pragma unroll
        for (int c = 0; c < 8; c++) acc[r][c] = 0.0f;

    for (int k0 = 0; k0 < K_DIM; k0 += BK) {
        // Cooperative load: 128 rows x 32 k-cols per tile, as 128x8 float4 loads.
        // 1024 float4 per tile, 256 threads -> 4 each. Coalesced along k.
#pragma unroll
        for (int i = 0; i < 4; i++) {
            int id  = tid + 256 * i;
            int row = id >> 3;        // 0..127
            int vc  = id & 7;         // float4 column 0..7
            int kk  = vc * 4;

            float4 a = *reinterpret_cast<const float4*>(
                &X[(size_t)(bm + row) * K_DIM + k0 + kk]);
            As[kk + 0][row] = a.x;
            As[kk + 1][row] = a.y;
            As[kk + 2][row] = a.z;
            As[kk + 3][row] = a.w;

            float4 b = *reinterpret_cast<const float4*>(
                &W1[(size_t)(bn + row) * K_DIM + k0 + kk]);
            Bs[kk + 0][row] = (b.x >= 0.0f) ? 1.0f : -1.0f;
            Bs[kk + 1][row] = (b.y >= 0.0f) ? 1.0f : -1.0f;
            Bs[kk + 2][row] = (b.z >= 0.0f) ? 1.0f : -1.0f;
            Bs[kk + 3][row] = (b.w >= 0.0f) ? 1.0f : -1.0f;
        }
        __syncthreads();

#pragma unroll
        for (int kk = 0; kk < BK; kk++) {
            // Vectorized smem reads; As row base is 16B aligned (PAD=4).
            float4 av0 = *reinterpret_cast<const float4*>(&As[kk][ty * 4]);
            float4 av1 = *reinterpret_cast<const float4*>(&As[kk][64 + ty * 4]);
            float4 bv0 = *reinterpret_cast<const float4*>(&Bs[kk][tx * 4]);
            float4 bv1 = *reinterpret_cast<const float4*>(&Bs[kk][64 + tx * 4]);
            float a[8] = {av0.x, av0.y, av0.z, av0.w, av1.x, av1.y, av1.z, av1.w};
            float b[8] = {bv0.x, bv0.y, bv0.z, bv0.w, bv1.x, bv1.y, bv1.z, bv1.w};
#pragma unroll
            for (int r = 0; r < 8; r++)
#pragma unroll
                for (int c = 0; c < 8; c++)
                    acc[r][c] = fmaf(a[r], b[c], acc[r][c]);
        }
        __syncthreads();
    }

    // Epilogue: p[r] = sum_c sign(acc[r][c]) * sign(W2[col(c)])
    // sign convention matches reference binarize: (v >= 0) -> +1.
    bool w2pos[8];
#pragma unroll
    for (int c = 0; c < 8; c++) {
        int col = bn + ((c < 4) ? (tx * 4 + c) : (64 + tx * 4 + (c - 4)));
        w2pos[c] = (W2[col] >= 0.0f);
    }

    float p[8];
#pragma unroll
    for (int r = 0; r < 8; r++) {
        float s = 0.0f;
#pragma unroll
        for (int c = 0; c < 8; c++) {
            bool hpos = (acc[r][c] >= 0.0f);
            s += (hpos == w2pos[c]) ? 1.0f : -1.0f;
        }
        p[r] = s;
    }

    // Reduce over the 16 tx-lanes (they share the same rows). Lanes 0..15 of a
    // warp have ty even, 16..31 ty odd, so width-16 shuffles reduce each group.
#pragma unroll
    for (int r = 0; r < 8; r++) {
#pragma unroll
        for (int off = 8; off >= 1; off >>= 1)
            p[r] += __shfl_down_sync(0xffffffffu, p[r], off, 16);
    }

    if (tx == 0) {
#pragma unroll
        for (int r = 0; r < 8; r++) {
            int row = bm + ((r < 4) ? (ty * 4 + r) : (64 + ty * 4 + (r - 4)));
            atomicAdd(&g_s[row], p[r]);
        }
    }
}

__global__ void finalize_kernel(float* __restrict__ out, int out_size) {
    int b = blockIdx.x * blockDim.x + threadIdx.x;
    if (b >= M_ROWS) return;
    float s = g_s[b];
    float o = 1.0f / (1.0f + expf(-s));        // sigmoid; saturates exactly to 0/1 for |s| large
    if (b < out_size) out[b] = o;
    int yi = M_ROWS + b;                        // y_hat = (out >= 0.5) <=> (s >= 0)
    if (yi < out_size) out[yi] = (s >= 0.0f) ? 1.0f : 0.0f;
}

extern "C" void kernel_launch(void* const* d_in, const int* in_sizes, int n_in,
                              void* d_out, int out_size) {
    const float* X  = (const float*)d_in[0];   // [16384, 4096]
    const float* W1 = (const float*)d_in[1];   // [4096, 4096]
    const float* W2 = (const float*)d_in[2];   // [1, 4096]
    float* out = (float*)d_out;

    zero_s_kernel<<<(M_ROWS + 255) / 256, 256>>>();

    dim3 grid(N_DIM / BN, M_ROWS / BM);        // (32, 128) = 4096 CTAs
    gemm_sign_kernel<<<grid, 256>>>(X, W1, W2);

    finalize_kernel<<<(M_ROWS + 255) / 256, 256>>>(out, out_size);
}

// round 6
// speedup vs baseline: 1.1468x; 1.1468x over previous
#include <cuda_runtime.h>
#include <math.h>
#include <stdint.h>

// ============================ problem dims =================================
#define M_ROWS 16384
#define K_DIM  4096
#define N_DIM  4096

// ============================ GEMM tiling ==================================
#define BM 128
#define BN 128
#define BK 16
#define PAD 4
#define KTILES (K_DIM / BK)   // 256

// Per-row signed popcount s[b] = sum_j sign(h[b,j])*sign(W2[j]); exact small
// integers in fp32 -> atomicAdd is order-independent & deterministic.
__device__ float g_s[M_ROWS];

// ============================ f32x2 helpers ================================
// Packed fp32 FMA (Blackwell). Each 32-bit lane is an IEEE fp32 FMA, so the
// per-element accumulation chain is bit-identical to scalar FFMA. We pack two
// *N columns* per accumulator; every output element keeps a strictly
// k-sequential single-accumulator fp32 chain (matches the reference GEMM's
// rounding order -> same pass behavior as the round-1 kernel).
__device__ __forceinline__ unsigned long long pack2(float lo, float hi) {
    unsigned long long d;
    asm("mov.b64 %0, {%1, %2};" : "=l"(d)
        : "r"(__float_as_uint(lo)), "r"(__float_as_uint(hi)));
    return d;
}
__device__ __forceinline__ void unpack2(unsigned long long v, float& lo, float& hi) {
    uint32_t a, b;
    asm("mov.b64 {%0, %1}, %2;" : "=r"(a), "=r"(b) : "l"(v));
    lo = __uint_as_float(a);
    hi = __uint_as_float(b);
}
#define FMA2(acc, a, b) \
    asm("fma.rn.f32x2 %0, %1, %2, %0;" : "+l"(acc) : "l"(a), "l"(b))

// ============================ kernels ======================================
__global__ void zero_s_kernel() {
    int i = blockIdx.x * blockDim.x + threadIdx.x;
    if (i < M_ROWS) g_s[i] = 0.0f;
}

// Fused GEMM: C = X @ sign(W1)^T in fp32 (k-sequential per element), epilogue
// reduces sign(C)*sign(W2) into g_s. W1 binarized at smem-store time.
__global__ __launch_bounds__(256, 2)
void gemm_sign_kernel(const float* __restrict__ X,
                      const float* __restrict__ W1,
                      const float* __restrict__ W2) {
    __shared__ float As[BK][BM + PAD];   // As[k][m]
    __shared__ float Bs[BK][BN + PAD];   // Bs[k][n], values +/-1

    const int bm  = blockIdx.y * BM;
    const int bn  = blockIdx.x * BN;
    const int tid = threadIdx.x;
    const int tx  = tid & 15;
    const int ty  = tid >> 4;

    // Per-tile loads: A tile 128x16 = 512 float4, B tile same; 256 threads ->
    // 2 float4 each per tile per matrix. Register-prefetch double buffering.
    const int row_a = (tid >> 2);            // 0..63 for j=0; +64 for j=1
    const int vc    = tid & 3;               // float4 col -> k = vc*4
    const int kk0   = vc * 4;

    // acc2[r][cp]: packed pair of n-columns. Mapping (same as round 1):
    //   cp 0,1 -> n = tx*4 + cp*2 + {0,1};  cp 2,3 -> n = 64 + tx*4 + (cp-2)*2 + {0,1}
    unsigned long long acc2[8][4];
#pragma unroll
    for (int r = 0; r < 8; r++)
#pragma unroll
        for (int cp = 0; cp < 4; cp++) acc2[r][cp] = pack2(0.f, 0.f);

    float4 pa[2], pb[2];
    // Prologue prefetch: tile 0.
#pragma unroll
    for (int j = 0; j < 2; j++) {
        int row = row_a + 64 * j;
        pa[j] = *reinterpret_cast<const float4*>(&X [(size_t)(bm + row) * K_DIM + kk0]);
        pb[j] = *reinterpret_cast<const float4*>(&W1[(size_t)(bn + row) * K_DIM + kk0]);
    }

    for (int t = 0; t < KTILES; t++) {
        // Store prefetched tile t into smem (A transposed; B binarized).
#pragma unroll
        for (int j = 0; j < 2; j++) {
            int row = row_a + 64 * j;
            As[kk0 + 0][row] = pa[j].x;
            As[kk0 + 1][row] = pa[j].y;
            As[kk0 + 2][row] = pa[j].z;
            As[kk0 + 3][row] = pa[j].w;
            Bs[kk0 + 0][row] = (pb[j].x >= 0.f) ? 1.f : -1.f;
            Bs[kk0 + 1][row] = (pb[j].y >= 0.f) ? 1.f : -1.f;
            Bs[kk0 + 2][row] = (pb[j].z >= 0.f) ? 1.f : -1.f;
            Bs[kk0 + 3][row] = (pb[j].w >= 0.f) ? 1.f : -1.f;
        }
        __syncthreads();

        // Prefetch tile t+1 from gmem while computing tile t from smem.
        if (t + 1 < KTILES) {
            const int kg = (t + 1) * BK + kk0;
#pragma unroll
            for (int j = 0; j < 2; j++) {
                int row = row_a + 64 * j;
                pa[j] = *reinterpret_cast<const float4*>(&X [(size_t)(bm + row) * K_DIM + kg]);
                pb[j] = *reinterpret_cast<const float4*>(&W1[(size_t)(bn + row) * K_DIM + kg]);
            }
        }

#pragma unroll
        for (int kk = 0; kk < BK; kk++) {
            float4 av0 = *reinterpret_cast<const float4*>(&As[kk][ty * 4]);
            float4 av1 = *reinterpret_cast<const float4*>(&As[kk][64 + ty * 4]);
            float4 bv0 = *reinterpret_cast<const float4*>(&Bs[kk][tx * 4]);
            float4 bv1 = *reinterpret_cast<const float4*>(&Bs[kk][64 + tx * 4]);

            unsigned long long pbv[4];
            pbv[0] = pack2(bv0.x, bv0.y);
            pbv[1] = pack2(bv0.z, bv0.w);
            pbv[2] = pack2(bv1.x, bv1.y);
            pbv[3] = pack2(bv1.z, bv1.w);

            float a[8] = {av0.x, av0.y, av0.z, av0.w,
                          av1.x, av1.y, av1.z, av1.w};
#pragma unroll
            for (int r = 0; r < 8; r++) {
                unsigned long long pav = pack2(a[r], a[r]);
                FMA2(acc2[r][0], pav, pbv[0]);
                FMA2(acc2[r][1], pav, pbv[1]);
                FMA2(acc2[r][2], pav, pbv[2]);
                FMA2(acc2[r][3], pav, pbv[3]);
            }
        }
        __syncthreads();
    }

    // --------------------------- epilogue -----------------------------------
    // sign convention matches reference binarize: (v >= 0) -> +1.
    bool w2pos[8];
#pragma unroll
    for (int c = 0; c < 8; c++) {
        int col = bn + ((c < 4) ? (tx * 4 + c) : (64 + tx * 4 + (c - 4)));
        w2pos[c] = (W2[col] >= 0.0f);
    }

    float p[8];
#pragma unroll
    for (int r = 0; r < 8; r++) {
        float s = 0.0f;
#pragma unroll
        for (int cp = 0; cp < 4; cp++) {
            float lo, hi;
            unpack2(acc2[r][cp], lo, hi);
            int c = cp * 2;                 // c, c+1 in round-1 c-indexing
            s += ((lo >= 0.f) == w2pos[c])     ? 1.f : -1.f;
            s += ((hi >= 0.f) == w2pos[c + 1]) ? 1.f : -1.f;
        }
        p[r] = s;
    }

    // Reduce over the 16 tx lanes (same rows), width-16 shuffles.
#pragma unroll
    for (int r = 0; r < 8; r++) {
#pragma unroll
        for (int off = 8; off >= 1; off >>= 1)
            p[r] += __shfl_down_sync(0xffffffffu, p[r], off, 16);
    }

    if (tx == 0) {
#pragma unroll
        for (int r = 0; r < 8; r++) {
            int row = bm + ((r < 4) ? (ty * 4 + r) : (64 + ty * 4 + (r - 4)));
            atomicAdd(&g_s[row], p[r]);
        }
    }
}

__global__ void finalize_kernel(float* __restrict__ out, int out_size) {
    int b = blockIdx.x * blockDim.x + threadIdx.x;
    if (b >= M_ROWS) return;
    float s = g_s[b];
    float o = 1.0f / (1.0f + expf(-s));
    if (b < out_size) out[b] = o;
    int yi = M_ROWS + b;
    if (yi < out_size) out[yi] = (s >= 0.0f) ? 1.0f : 0.0f;
}

// ============================ launcher =====================================
extern "C" void kernel_launch(void* const* d_in, const int* in_sizes, int n_in,
                              void* d_out, int out_size) {
    const float* X  = (const float*)d_in[0];   // [16384, 4096]
    const float* W1 = (const float*)d_in[1];   // [4096, 4096]
    const float* W2 = (const float*)d_in[2];   // [4096]
    float* out = (float*)d_out;

    zero_s_kernel<<<(M_ROWS + 255) / 256, 256>>>();

    dim3 grid(N_DIM / BN, M_ROWS / BM);        // (32, 128)
    gemm_sign_kernel<<<grid, 256>>>(X, W1, W2);

    finalize_kernel<<<(M_ROWS + 255) / 256, 256>>>(out, out_size);
}

// round 7
// speedup vs baseline: 2.3771x; 2.0728x over previous
#include <cuda_runtime.h>
#include <cuda_bf16.h>
#include <math.h>
#include <stdint.h>

// ============================ problem dims =================================
#define M_ROWS 16384
#define K_DIM  4096
#define N_DIM  4096

// ============================ GEMM tiling ==================================
#define BM 128
#define BN 128
#define BK 32                       // bf16 per k-chunk -> 64B rows in smem
#define KIT (K_DIM / BK)            // 128 k-iterations
#define NSPLIT 3
#define NSTAGES 4

#define TILE_BYTES (128 * 64)       // 8 KB: 128 rows x 32 bf16
#define STAGE_BYTES (4 * TILE_BYTES)        // 3 A-split tiles + 1 B tile = 32 KB
#define SMEM_TILES_OFF 1024
#define DYN_SMEM (SMEM_TILES_OFF + NSTAGES * STAGE_BYTES)   // 1 KB hdr + 128 KB

// Marginal threshold: |h_tc| < DELTA -> recompute with sequential fp32.
// |h_tc - h_seq| <= ~1e-3 abs, so DELTA=0.02 gives ~20x safety margin.
#define DELTA 0.02f
#define MAXW  (4u * 1024u * 1024u)

// ============================ device scratch ===============================
__device__ float g_s[M_ROWS];
__device__ unsigned int g_cnt;
__device__ unsigned int g_wl[MAXW];   // packed: sign<<31 | m*4096 + n
__device__ __nv_bfloat16 g_X0[(size_t)M_ROWS * K_DIM];
__device__ __nv_bfloat16 g_X1[(size_t)M_ROWS * K_DIM];
__device__ __nv_bfloat16 g_X2[(size_t)M_ROWS * K_DIM];
__device__ __nv_bfloat16 g_Wb[(size_t)N_DIM * K_DIM];     // sign(W1) as bf16 +/-1

// ============================ PTX helpers ==================================
__device__ __forceinline__ uint32_t smem_u32(const void* p) {
    uint32_t a;
    asm("{ .reg .u64 t; cvta.to.shared.u64 t, %1; cvt.u32.u64 %0, t; }"
        : "=r"(a) : "l"(p));
    return a;
}

#define CP_ASYNC16(dst, src) \
    asm volatile("cp.async.cg.shared.global [%0], [%1], 16;" \
                 :: "r"(dst), "l"(src) : "memory")
#define CP_COMMIT() asm volatile("cp.async.commit_group;" ::: "memory")
#define CP_WAIT2()  asm volatile("cp.async.wait_group 2;" ::: "memory")

__device__ __forceinline__ void ldm_x4(uint32_t* r, uint32_t addr) {
    asm volatile("ldmatrix.sync.aligned.m8n8.x4.shared.b16 {%0,%1,%2,%3}, [%4];"
                 : "=r"(r[0]), "=r"(r[1]), "=r"(r[2]), "=r"(r[3]) : "r"(addr));
}

__device__ __forceinline__ void mma_bf16(float* c, const uint32_t* a,
                                         const uint32_t* b) {
    asm volatile(
        "mma.sync.aligned.m16n8k16.row.col.f32.bf16.bf16.f32 "
        "{%0,%1,%2,%3}, {%4,%5,%6,%7}, {%8,%9}, {%0,%1,%2,%3};"
        : "+f"(c[0]), "+f"(c[1]), "+f"(c[2]), "+f"(c[3])
        : "r"(a[0]), "r"(a[1]), "r"(a[2]), "r"(a[3]), "r"(b[0]), "r"(b[1]));
}

// smem tile addressing: 128 rows x 64B, 4x 16B chunks/row, swizzled.
__device__ __forceinline__ uint32_t swz(uint32_t base, int row, int chunk) {
    return base + row * 64 + ((chunk ^ ((row >> 1) & 3)) << 4);
}

// ============================ prepass kernels ==============================
__global__ void zero_s_kernel() {
    int i = blockIdx.x * blockDim.x + threadIdx.x;
    if (i < M_ROWS) g_s[i] = 0.0f;
    if (i == 0) g_cnt = 0u;
}

__global__ void binarize_w1_kernel(const float* __restrict__ W1) {
    size_t i = ((size_t)blockIdx.x * blockDim.x + threadIdx.x) * 4;
    float4 v = *reinterpret_cast<const float4*>(W1 + i);
    const unsigned short P = 0x3F80, N = 0xBF80;   // bf16 +1 / -1
    ushort4 o;
    o.x = (v.x >= 0.f) ? P : N;
    o.y = (v.y >= 0.f) ? P : N;
    o.z = (v.z >= 0.f) ? P : N;
    o.w = (v.w >= 0.f) ? P : N;
    *reinterpret_cast<ushort4*>(&g_Wb[i]) = o;
}

// 3-way bf16 split: x = b0+b1+b2 captures >= 24 mantissa bits; products with
// +/-1 are exact, so h_tc differs from h only by fp32 accumulation order.
__global__ void split_x_kernel(const float* __restrict__ X) {
    size_t i = ((size_t)blockIdx.x * blockDim.x + threadIdx.x) * 4;
    float4 v = *reinterpret_cast<const float4*>(X + i);
    float f[4] = {v.x, v.y, v.z, v.w};
    ushort4 o0, o1, o2;
    unsigned short* p0 = &o0.x;
    unsigned short* p1 = &o1.x;
    unsigned short* p2 = &o2.x;
#pragma unroll
    for (int j = 0; j < 4; ++j) {
        float x = f[j];
        __nv_bfloat16 b0 = __float2bfloat16(x);
        float r1 = x - __bfloat162float(b0);
        __nv_bfloat16 b1 = __float2bfloat16(r1);
        float r2 = r1 - __bfloat162float(b1);
        __nv_bfloat16 b2 = __float2bfloat16(r2);
        p0[j] = __bfloat16_as_ushort(b0);
        p1[j] = __bfloat16_as_ushort(b1);
        p2[j] = __bfloat16_as_ushort(b2);
    }
    *reinterpret_cast<ushort4*>(&g_X0[i]) = o0;
    *reinterpret_cast<ushort4*>(&g_X1[i]) = o1;
    *reinterpret_cast<ushort4*>(&g_X2[i]) = o2;
}

// ============================ main GEMM (tensor) ===========================
// 8 warps (4m x 2n), warp tile 32x64, mma.sync m16n8k16 bf16, 4-stage
// cp.async pipeline. Epilogue: signed popcount vs sign(W2) -> atomicAdd g_s,
// and marginal elements (|h| < DELTA) pushed to worklist for fp32 recheck.
__global__ __launch_bounds__(256, 1)
void gemm_mma_kernel(const float* __restrict__ W2) {
    extern __shared__ char dsm[];
    const uint32_t sb = smem_u32(dsm);
    float* w2s = reinterpret_cast<float*>(dsm);          // [128]
    const uint32_t tiles = sb + SMEM_TILES_OFF;

    const int tid  = threadIdx.x;
    const int wid  = tid >> 5;
    const int lane = tid & 31;
    const int wm   = wid >> 1;
    const int wn   = wid & 1;
    const int WM   = wm * 32;
    const int WN   = wn * 64;

    // Supertiled CTA order: 8 m-blocks x 32 n-blocks per supertile.
    const int bid = blockIdx.x;
    const int sid = bid >> 8;
    const int rem = bid & 255;
    const int bm  = (sid * 8 + (rem & 7)) * BM;
    const int bn  = (rem >> 3) * BN;

    if (tid < BN) w2s[tid] = (W2[bn + tid] >= 0.f) ? 1.f : -1.f;

    const __nv_bfloat16* abase[NSPLIT] = {
        g_X0 + (size_t)bm * K_DIM,
        g_X1 + (size_t)bm * K_DIM,
        g_X2 + (size_t)bm * K_DIM };
    const __nv_bfloat16* bbase = g_Wb + (size_t)bn * K_DIM;

#define LOAD_STAGE(stg, kt) do {                                              \
    const int _k0 = (kt) * BK;                                                \
    const uint32_t _sb0 = tiles + (stg) * STAGE_BYTES;                        \
    _Pragma("unroll")                                                         \
    for (int _t = 0; _t < 4; ++_t) {                                          \
        const __nv_bfloat16* _g = (_t < 3) ? abase[_t] : bbase;               \
        const uint32_t _tb = _sb0 + _t * TILE_BYTES;                          \
        _Pragma("unroll")                                                     \
        for (int _j = 0; _j < 2; ++_j) {                                      \
            int _id  = tid + _j * 256;                                        \
            int _row = _id >> 2;                                              \
            int _c   = _id & 3;                                               \
            CP_ASYNC16(swz(_tb, _row, _c),                                    \
                       _g + (size_t)_row * K_DIM + _k0 + _c * 8);             \
        }                                                                     \
    }                                                                         \
    CP_COMMIT();                                                              \
} while (0)

    LOAD_STAGE(0, 0);
    LOAD_STAGE(1, 1);
    LOAD_STAGE(2, 2);

    float acc[2][8][4];
#pragma unroll
    for (int mi = 0; mi < 2; ++mi)
#pragma unroll
        for (int ni = 0; ni < 8; ++ni)
#pragma unroll
            for (int e = 0; e < 4; ++e) acc[mi][ni][e] = 0.f;

    const int arow  = WM + (lane & 7) + ((lane >> 3) & 1) * 8;
    const int achk  = lane >> 4;
    const int brow0 = WN + (lane & 7) + ((lane >> 4) & 1) * 8;
    const int bchk  = (lane >> 3) & 1;

    for (int it = 0; it < KIT; ++it) {
        CP_WAIT2();
        __syncthreads();

        // One commit per iteration ALWAYS (empty group in the tail) so the
        // wait_group accounting keeps consumed stages complete.
        if (it + 3 < KIT) LOAD_STAGE((it + 3) & 3, it + 3);
        else              CP_COMMIT();

        const uint32_t s0 = tiles + (it & 3) * STAGE_BYTES;
        const uint32_t bt = s0 + 3 * TILE_BYTES;

#pragma unroll
        for (int ks = 0; ks < 2; ++ks) {
            uint32_t br[16];
#pragma unroll
            for (int gi = 0; gi < 4; ++gi)
                ldm_x4(&br[gi * 4], swz(bt, brow0 + gi * 16, 2 * ks + bchk));

#pragma unroll
            for (int p = 0; p < NSPLIT; ++p) {
                const uint32_t at = s0 + p * TILE_BYTES;
                uint32_t ar[8];
                ldm_x4(&ar[0], swz(at, arow,      2 * ks + achk));
                ldm_x4(&ar[4], swz(at, arow + 16, 2 * ks + achk));
#pragma unroll
                for (int mi = 0; mi < 2; ++mi)
#pragma unroll
                    for (int ni = 0; ni < 8; ++ni)
                        mma_bf16(acc[mi][ni], &ar[mi * 4],
                                 &br[(ni >> 1) * 4 + (ni & 1) * 2]);
            }
        }
        __syncthreads();
    }

    // --------------------------- epilogue ----------------------------------
    // acc[mi][ni][e]: m = WM + mi*16 + (lane>>2) + (e>=2)*8
    //                 n = WN + ni*8 + (lane&3)*2 + (e&1)
    float rs[2][2] = {{0.f, 0.f}, {0.f, 0.f}};
#pragma unroll
    for (int mi = 0; mi < 2; ++mi)
#pragma unroll
        for (int ni = 0; ni < 8; ++ni)
#pragma unroll
            for (int e = 0; e < 4; ++e) {
                float h = acc[mi][ni][e];
                int nl = WN + ni * 8 + (lane & 3) * 2 + (e & 1);
                float w = w2s[nl];
                bool pos = (h >= 0.f);
                rs[mi][e >> 1] += pos ? w : -w;
                if (fabsf(h) < DELTA) {   // marginal: queue fp32 recheck
                    int m = bm + WM + mi * 16 + (lane >> 2) + (e >> 1) * 8;
                    unsigned idx = atomicAdd(&g_cnt, 1u);
                    if (idx < MAXW)
                        g_wl[idx] = (unsigned)(m * 4096 + (bn + nl)) |
                                    (pos ? 0x80000000u : 0u);
                }
            }

#pragma unroll
    for (int mi = 0; mi < 2; ++mi)
#pragma unroll
        for (int eh = 0; eh < 2; ++eh) {
            rs[mi][eh] += __shfl_xor_sync(0xffffffffu, rs[mi][eh], 1);
            rs[mi][eh] += __shfl_xor_sync(0xffffffffu, rs[mi][eh], 2);
        }

    if ((lane & 3) == 0) {
#pragma unroll
        for (int mi = 0; mi < 2; ++mi)
#pragma unroll
            for (int eh = 0; eh < 2; ++eh) {
                int m = bm + WM + mi * 16 + (lane >> 2) + eh * 8;
                atomicAdd(&g_s[m], rs[mi][eh]);
            }
    }
#undef LOAD_STAGE
}

// ===================== correction: sequential fp32 recheck =================
// For each marginal element, recompute h with a strictly k-ascending
// single-accumulator fp32 FMA chain (the exact arithmetic of the round-1
// kernel, which empirically matches the reference's rounding). Apply +/-2*w2
// delta if the sign flips. Deltas are additive -> order-independent.
__global__ void correction_kernel(const float* __restrict__ X,
                                  const float* __restrict__ W1,
                                  const float* __restrict__ W2) {
    unsigned cnt = g_cnt;
    if (cnt > MAXW) cnt = MAXW;
    for (unsigned i = blockIdx.x * blockDim.x + threadIdx.x; i < cnt;
         i += gridDim.x * blockDim.x) {
        unsigned e = g_wl[i];
        bool sign_tc = (e >> 31) != 0u;
        unsigned v = e & 0x7FFFFFFFu;
        int m = (int)(v >> 12);
        int n = (int)(v & 4095u);
        const float* xr = X  + (size_t)m * K_DIM;
        const float* wr = W1 + (size_t)n * K_DIM;
        float acc = 0.f;
        for (int k = 0; k < K_DIM; k += 4) {
            float4 xv = *reinterpret_cast<const float4*>(xr + k);
            float4 wv = *reinterpret_cast<const float4*>(wr + k);
            acc = fmaf(xv.x, (wv.x >= 0.f) ? 1.f : -1.f, acc);
            acc = fmaf(xv.y, (wv.y >= 0.f) ? 1.f : -1.f, acc);
            acc = fmaf(xv.z, (wv.z >= 0.f) ? 1.f : -1.f, acc);
            acc = fmaf(xv.w, (wv.w >= 0.f) ? 1.f : -1.f, acc);
        }
        bool sign_seq = (acc >= 0.f);
        if (sign_seq != sign_tc) {
            float w = (W2[n] >= 0.f) ? 1.f : -1.f;
            atomicAdd(&g_s[m], sign_seq ? 2.f * w : -2.f * w);
        }
    }
}

// ============================ finalize =====================================
__global__ void finalize_kernel(float* __restrict__ out, int out_size) {
    int b = blockIdx.x * blockDim.x + threadIdx.x;
    if (b >= M_ROWS) return;
    float s = g_s[b];
    float o = 1.0f / (1.0f + expf(-s));
    if (b < out_size) out[b] = o;
    int yi = M_ROWS + b;
    if (yi < out_size) out[yi] = (s >= 0.0f) ? 1.0f : 0.0f;
}

// ============================ launcher =====================================
extern "C" void kernel_launch(void* const* d_in, const int* in_sizes, int n_in,
                              void* d_out, int out_size) {
    const float* X  = (const float*)d_in[0];   // [16384, 4096]
    const float* W1 = (const float*)d_in[1];   // [4096, 4096]
    const float* W2 = (const float*)d_in[2];   // [4096]
    float* out = (float*)d_out;

    cudaFuncSetAttribute(gemm_mma_kernel,
                         cudaFuncAttributeMaxDynamicSharedMemorySize, DYN_SMEM);

    binarize_w1_kernel<<<(N_DIM * (size_t)K_DIM) / (4 * 256), 256>>>(W1);
    split_x_kernel<<<(M_ROWS * (size_t)K_DIM) / (4 * 256), 256>>>(X);
    zero_s_kernel<<<(M_ROWS + 255) / 256, 256>>>();

    gemm_mma_kernel<<<(M_ROWS / BM) * (N_DIM / BN), 256, DYN_SMEM>>>(W2);

    correction_kernel<<<1024, 128>>>(X, W1, W2);

    finalize_kernel<<<(M_ROWS + 255) / 256, 256>>>(out, out_size);
}

// round 8
// speedup vs baseline: 3.8873x; 1.6354x over previous
#include <cuda_runtime.h>
#include <cuda_bf16.h>
#include <math.h>
#include <stdint.h>

// ============================ problem dims =================================
#define M_ROWS 16384
#define K_DIM  4096
#define N_DIM  4096

// ============================ GEMM tiling ==================================
#define BM 128
#define BN 128
#define BK 32                       // bf16 per k-chunk -> 64B rows in smem
#define KIT (K_DIM / BK)            // 128 k-iterations
#define NSPLIT 2
#define NSTAGES 4

#define TILE_BYTES (128 * 64)       // 8 KB: 128 rows x 32 bf16
#define STAGE_BYTES (3 * TILE_BYTES)        // 2 A-split tiles + 1 B tile = 24 KB
#define SMEM_TILES_OFF 1024
#define DYN_SMEM (SMEM_TILES_OFF + NSTAGES * STAGE_BYTES)   // ~97 KB -> 2 CTAs/SM

// Marginal threshold: |h_tc| < DELTA -> recompute with sequential fp32.
// 2-split truncation + accumulation-order sigma ~3e-4 -> DELTA is >60 sigma.
#define DELTA 0.02f
#define MAXW  (4u * 1024u * 1024u)

// ============================ device scratch ===============================
__device__ float g_s[M_ROWS];
__device__ unsigned int g_cnt;
__device__ unsigned int g_wl[MAXW];   // packed: sign<<31 | m*4096 + n
__device__ __nv_bfloat16 g_X0[(size_t)M_ROWS * K_DIM];
__device__ __nv_bfloat16 g_X1[(size_t)M_ROWS * K_DIM];
__device__ __nv_bfloat16 g_Wb[(size_t)N_DIM * K_DIM];     // sign(W1) as bf16 +/-1

// ============================ PTX helpers ==================================
__device__ __forceinline__ uint32_t smem_u32(const void* p) {
    uint32_t a;
    asm("{ .reg .u64 t; cvta.to.shared.u64 t, %1; cvt.u32.u64 %0, t; }"
        : "=r"(a) : "l"(p));
    return a;
}

#define CP_ASYNC16(dst, src) \
    asm volatile("cp.async.cg.shared.global [%0], [%1], 16;" \
                 :: "r"(dst), "l"(src) : "memory")
#define CP_COMMIT() asm volatile("cp.async.commit_group;" ::: "memory")
#define CP_WAIT2()  asm volatile("cp.async.wait_group 2;" ::: "memory")

__device__ __forceinline__ void ldm_x4(uint32_t* r, uint32_t addr) {
    asm volatile("ldmatrix.sync.aligned.m8n8.x4.shared.b16 {%0,%1,%2,%3}, [%4];"
                 : "=r"(r[0]), "=r"(r[1]), "=r"(r[2]), "=r"(r[3]) : "r"(addr));
}

__device__ __forceinline__ void mma_bf16(float* c, const uint32_t* a,
                                         const uint32_t* b) {
    asm volatile(
        "mma.sync.aligned.m16n8k16.row.col.f32.bf16.bf16.f32 "
        "{%0,%1,%2,%3}, {%4,%5,%6,%7}, {%8,%9}, {%0,%1,%2,%3};"
        : "+f"(c[0]), "+f"(c[1]), "+f"(c[2]), "+f"(c[3])
        : "r"(a[0]), "r"(a[1]), "r"(a[2]), "r"(a[3]), "r"(b[0]), "r"(b[1]));
}

// smem tile addressing: 128 rows x 64B, 4x 16B chunks/row, swizzled.
__device__ __forceinline__ uint32_t swz(uint32_t base, int row, int chunk) {
    return base + row * 64 + ((chunk ^ ((row >> 1) & 3)) << 4);
}

// ============================ prepass kernels ==============================
__global__ void zero_s_kernel() {
    int i = blockIdx.x * blockDim.x + threadIdx.x;
    if (i < M_ROWS) g_s[i] = 0.0f;
    if (i == 0) g_cnt = 0u;
}

__global__ void binarize_w1_kernel(const float* __restrict__ W1) {
    size_t i = ((size_t)blockIdx.x * blockDim.x + threadIdx.x) * 4;
    float4 v = *reinterpret_cast<const float4*>(W1 + i);
    const unsigned short P = 0x3F80, N = 0xBF80;   // bf16 +1 / -1
    ushort4 o;
    o.x = (v.x >= 0.f) ? P : N;
    o.y = (v.y >= 0.f) ? P : N;
    o.z = (v.z >= 0.f) ? P : N;
    o.w = (v.w >= 0.f) ? P : N;
    *reinterpret_cast<ushort4*>(&g_Wb[i]) = o;
}

// 2-way bf16 split: x ~ b0+b1 captures ~17 mantissa bits; residual
// <= 2^-18 |x| per element. Products with +/-1 are exact; the resulting
// |h_tc - h_seq| stays far below DELTA, and the correction pass makes the
// final signs exactly match the sequential-fp32 computation.
__global__ void split_x_kernel(const float* __restrict__ X) {
    size_t i = ((size_t)blockIdx.x * blockDim.x + threadIdx.x) * 4;
    float4 v = *reinterpret_cast<const float4*>(X + i);
    float f[4] = {v.x, v.y, v.z, v.w};
    ushort4 o0, o1;
    unsigned short* p0 = &o0.x;
    unsigned short* p1 = &o1.x;
#pragma unroll
    for (int j = 0; j < 4; ++j) {
        float x = f[j];
        __nv_bfloat16 b0 = __float2bfloat16(x);
        float r1 = x - __bfloat162float(b0);
        __nv_bfloat16 b1 = __float2bfloat16(r1);
        p0[j] = __bfloat16_as_ushort(b0);
        p1[j] = __bfloat16_as_ushort(b1);
    }
    *reinterpret_cast<ushort4*>(&g_X0[i]) = o0;
    *reinterpret_cast<ushort4*>(&g_X1[i]) = o1;
}

// ============================ main GEMM (tensor) ===========================
// 8 warps (4m x 2n), warp tile 32x64, mma.sync m16n8k16 bf16, 4-stage
// cp.async pipeline, 2 CTAs/SM. Epilogue: signed popcount vs sign(W2)
// -> atomicAdd g_s; marginal elements (|h| < DELTA) -> worklist.
__global__ __launch_bounds__(256, 2)
void gemm_mma_kernel(const float* __restrict__ W2) {
    extern __shared__ char dsm[];
    const uint32_t sb = smem_u32(dsm);
    float* w2s = reinterpret_cast<float*>(dsm);          // [128]
    const uint32_t tiles = sb + SMEM_TILES_OFF;

    const int tid  = threadIdx.x;
    const int wid  = tid >> 5;
    const int lane = tid & 31;
    const int wm   = wid >> 1;
    const int wn   = wid & 1;
    const int WM   = wm * 32;
    const int WN   = wn * 64;

    // Supertiled CTA order: 8 m-blocks x 32 n-blocks per supertile.
    const int bid = blockIdx.x;
    const int sid = bid >> 8;
    const int rem = bid & 255;
    const int bm  = (sid * 8 + (rem & 7)) * BM;
    const int bn  = (rem >> 3) * BN;

    if (tid < BN) w2s[tid] = (W2[bn + tid] >= 0.f) ? 1.f : -1.f;

    const __nv_bfloat16* abase[NSPLIT] = {
        g_X0 + (size_t)bm * K_DIM,
        g_X1 + (size_t)bm * K_DIM };
    const __nv_bfloat16* bbase = g_Wb + (size_t)bn * K_DIM;

#define LOAD_STAGE(stg, kt) do {                                              \
    const int _k0 = (kt) * BK;                                                \
    const uint32_t _sb0 = tiles + (stg) * STAGE_BYTES;                        \
    _Pragma("unroll")                                                         \
    for (int _t = 0; _t < 3; ++_t) {                                          \
        const __nv_bfloat16* _g = (_t < 2) ? abase[_t] : bbase;               \
        const uint32_t _tb = _sb0 + _t * TILE_BYTES;                          \
        _Pragma("unroll")                                                     \
        for (int _j = 0; _j < 2; ++_j) {                                      \
            int _id  = tid + _j * 256;                                        \
            int _row = _id >> 2;                                              \
            int _c   = _id & 3;                                               \
            CP_ASYNC16(swz(_tb, _row, _c),                                    \
                       _g + (size_t)_row * K_DIM + _k0 + _c * 8);             \
        }                                                                     \
    }                                                                         \
    CP_COMMIT();                                                              \
} while (0)

    LOAD_STAGE(0, 0);
    LOAD_STAGE(1, 1);
    LOAD_STAGE(2, 2);

    float acc[2][8][4];
#pragma unroll
    for (int mi = 0; mi < 2; ++mi)
#pragma unroll
        for (int ni = 0; ni < 8; ++ni)
#pragma unroll
            for (int e = 0; e < 4; ++e) acc[mi][ni][e] = 0.f;

    const int arow  = WM + (lane & 7) + ((lane >> 3) & 1) * 8;
    const int achk  = lane >> 4;
    const int brow0 = WN + (lane & 7) + ((lane >> 4) & 1) * 8;
    const int bchk  = (lane >> 3) & 1;

    for (int it = 0; it < KIT; ++it) {
        CP_WAIT2();
        __syncthreads();

        // One commit per iteration ALWAYS (empty group in the tail) so the
        // wait_group accounting keeps consumed stages complete.
        if (it + 3 < KIT) LOAD_STAGE((it + 3) & 3, it + 3);
        else              CP_COMMIT();

        const uint32_t s0 = tiles + (it & 3) * STAGE_BYTES;
        const uint32_t bt = s0 + 2 * TILE_BYTES;

#pragma unroll
        for (int ks = 0; ks < 2; ++ks) {
            uint32_t br[16];
#pragma unroll
            for (int gi = 0; gi < 4; ++gi)
                ldm_x4(&br[gi * 4], swz(bt, brow0 + gi * 16, 2 * ks + bchk));

#pragma unroll
            for (int p = 0; p < NSPLIT; ++p) {
                const uint32_t at = s0 + p * TILE_BYTES;
                uint32_t ar[8];
                ldm_x4(&ar[0], swz(at, arow,      2 * ks + achk));
                ldm_x4(&ar[4], swz(at, arow + 16, 2 * ks + achk));
#pragma unroll
                for (int mi = 0; mi < 2; ++mi)
#pragma unroll
                    for (int ni = 0; ni < 8; ++ni)
                        mma_bf16(acc[mi][ni], &ar[mi * 4],
                                 &br[(ni >> 1) * 4 + (ni & 1) * 2]);
            }
        }
        __syncthreads();
    }

    // --------------------------- epilogue ----------------------------------
    // acc[mi][ni][e]: m = WM + mi*16 + (lane>>2) + (e>=2)*8
    //                 n = WN + ni*8 + (lane&3)*2 + (e&1)
    float rs[2][2] = {{0.f, 0.f}, {0.f, 0.f}};
#pragma unroll
    for (int mi = 0; mi < 2; ++mi)
#pragma unroll
        for (int ni = 0; ni < 8; ++ni)
#pragma unroll
            for (int e = 0; e < 4; ++e) {
                float h = acc[mi][ni][e];
                int nl = WN + ni * 8 + (lane & 3) * 2 + (e & 1);
                float w = w2s[nl];
                bool pos = (h >= 0.f);
                rs[mi][e >> 1] += pos ? w : -w;
                if (fabsf(h) < DELTA) {   // marginal: queue fp32 recheck
                    int m = bm + WM + mi * 16 + (lane >> 2) + (e >> 1) * 8;
                    unsigned idx = atomicAdd(&g_cnt, 1u);
                    if (idx < MAXW)
                        g_wl[idx] = (unsigned)(m * 4096 + (bn + nl)) |
                                    (pos ? 0x80000000u : 0u);
                }
            }

#pragma unroll
    for (int mi = 0; mi < 2; ++mi)
#pragma unroll
        for (int eh = 0; eh < 2; ++eh) {
            rs[mi][eh] += __shfl_xor_sync(0xffffffffu, rs[mi][eh], 1);
            rs[mi][eh] += __shfl_xor_sync(0xffffffffu, rs[mi][eh], 2);
        }

    if ((lane & 3) == 0) {
#pragma unroll
        for (int mi = 0; mi < 2; ++mi)
#pragma unroll
            for (int eh = 0; eh < 2; ++eh) {
                int m = bm + WM + mi * 16 + (lane >> 2) + eh * 8;
                atomicAdd(&g_s[m], rs[mi][eh]);
            }
    }
#undef LOAD_STAGE
}

// ===================== correction: sequential fp32 recheck =================
// Recompute marginal h with a strictly k-ascending single-accumulator fp32
// FMA chain (round-1 arithmetic). Apply +/-2*w2 delta on sign flip.
__global__ void correction_kernel(const float* __restrict__ X,
                                  const float* __restrict__ W1,
                                  const float* __restrict__ W2) {
    unsigned cnt = g_cnt;
    if (cnt > MAXW) cnt = MAXW;
    for (unsigned i = blockIdx.x * blockDim.x + threadIdx.x; i < cnt;
         i += gridDim.x * blockDim.x) {
        unsigned e = g_wl[i];
        bool sign_tc = (e >> 31) != 0u;
        unsigned v = e & 0x7FFFFFFFu;
        int m = (int)(v >> 12);
        int n = (int)(v & 4095u);
        const float* xr = X  + (size_t)m * K_DIM;
        const float* wr = W1 + (size_t)n * K_DIM;
        float acc = 0.f;
        for (int k = 0; k < K_DIM; k += 4) {
            float4 xv = *reinterpret_cast<const float4*>(xr + k);
            float4 wv = *reinterpret_cast<const float4*>(wr + k);
            acc = fmaf(xv.x, (wv.x >= 0.f) ? 1.f : -1.f, acc);
            acc = fmaf(xv.y, (wv.y >= 0.f) ? 1.f : -1.f, acc);
            acc = fmaf(xv.z, (wv.z >= 0.f) ? 1.f : -1.f, acc);
            acc = fmaf(xv.w, (wv.w >= 0.f) ? 1.f : -1.f, acc);
        }
        bool sign_seq = (acc >= 0.f);
        if (sign_seq != sign_tc) {
            float w = (W2[n] >= 0.f) ? 1.f : -1.f;
            atomicAdd(&g_s[m], sign_seq ? 2.f * w : -2.f * w);
        }
    }
}

// ============================ finalize =====================================
__global__ void finalize_kernel(float* __restrict__ out, int out_size) {
    int b = blockIdx.x * blockDim.x + threadIdx.x;
    if (b >= M_ROWS) return;
    float s = g_s[b];
    float o = 1.0f / (1.0f + expf(-s));
    if (b < out_size) out[b] = o;
    int yi = M_ROWS + b;
    if (yi < out_size) out[yi] = (s >= 0.0f) ? 1.0f : 0.0f;
}

// ============================ launcher =====================================
extern "C" void kernel_launch(void* const* d_in, const int* in_sizes, int n_in,
                              void* d_out, int out_size) {
    const float* X  = (const float*)d_in[0];   // [16384, 4096]
    const float* W1 = (const float*)d_in[1];   // [4096, 4096]
    const float* W2 = (const float*)d_in[2];   // [4096]
    float* out = (float*)d_out;

    cudaFuncSetAttribute(gemm_mma_kernel,
                         cudaFuncAttributeMaxDynamicSharedMemorySize, DYN_SMEM);

    binarize_w1_kernel<<<(N_DIM * (size_t)K_DIM) / (4 * 256), 256>>>(W1);
    split_x_kernel<<<(M_ROWS * (size_t)K_DIM) / (4 * 256), 256>>>(X);
    zero_s_kernel<<<(M_ROWS + 255) / 256, 256>>>();

    gemm_mma_kernel<<<(M_ROWS / BM) * (N_DIM / BN), 256, DYN_SMEM>>>(W2);

    correction_kernel<<<1024, 128>>>(X, W1, W2);

    finalize_kernel<<<(M_ROWS + 255) / 256, 256>>>(out, out_size);
}